// round 16
// baseline (speedup 1.0000x reference)
#include <cuda_runtime.h>
#include <cuda_fp16.h>
#include <cstdint>

#define HDIM 1024
#define NEXP 64
#define KTOP 8
#define BM   64
#define KC   64
#define NCHUNK 16
#define NTHREADS 256

#define B_TILE 16384                     // 2 splits x 4 kt x 2 nh x 2 ntp x 32 x 16B
#define AF_BASE (3 * B_TILE)             // A-frag region after 3-stage B ring
#define AF_BUF  16384                    // per buffer: 2 splits x 8192
#define SMEM_TOTAL (AF_BASE + 2 * AF_BUF)  // 81920 B/CTA -> 2 CTAs/SM

#define MSCALE   2048.0f                 // 2^11 pre-scale for mid splits
#define MSCALE_I 4.8828125e-4f           // 2^-11

__device__ unsigned short g_wp[2 * 64 * 2 * 2 * 32 * 8];  // W fp16 splits, frag-permuted
__device__ float    g_esum[NEXP];
__device__ int      g_ecnt[NEXP];
__device__ unsigned g_done = 0;

__device__ __forceinline__ unsigned smem_u32(const void* p) {
    return (unsigned)__cvta_generic_to_shared(p);
}
__device__ __forceinline__ void cp16(unsigned dst, const void* src) {
    asm volatile("cp.async.cg.shared.global [%0], [%1], 16;\n" :: "r"(dst), "l"(src));
}
__device__ __forceinline__ void cp_commit() { asm volatile("cp.async.commit_group;\n"); }
__device__ __forceinline__ void cp_wait1()  { asm volatile("cp.async.wait_group 1;\n" ::: "memory"); }

__device__ __forceinline__ void lds128(uint32_t* r, unsigned a) {
    asm volatile("ld.shared.v4.u32 {%0,%1,%2,%3}, [%4];"
                 : "=r"(r[0]), "=r"(r[1]), "=r"(r[2]), "=r"(r[3]) : "r"(a));
}
__device__ __forceinline__ void sts128(unsigned a, const uint32_t* v) {
    asm volatile("st.shared.v4.b32 [%0], {%1,%2,%3,%4};"
                 :: "r"(a), "r"(v[0]), "r"(v[1]), "r"(v[2]), "r"(v[3]));
}
// D(16x8,f32) += A(16x16,f16 row) x B(16x8,f16 col)
__device__ __forceinline__ void mma16816(float* d, const uint32_t* a, const uint32_t* b) {
    asm volatile("mma.sync.aligned.m16n8k16.row.col.f32.f16.f16.f32 "
                 "{%0,%1,%2,%3}, {%4,%5,%6,%7}, {%8,%9}, {%0,%1,%2,%3};"
                 : "+f"(d[0]), "+f"(d[1]), "+f"(d[2]), "+f"(d[3])
                 : "r"(a[0]), "r"(a[1]), "r"(a[2]), "r"(a[3]), "r"(b[0]), "r"(b[1]));
}
__device__ __forceinline__ uint32_t h2bits(__half2 h) {
    return *reinterpret_cast<uint32_t*>(&h);
}

// Split W into fp16 hi + (mid * 2^11), stored in B-fragment-permuted layout.
__global__ void wsplit_k(const float* __restrict__ W) {
    int i = blockIdx.x * 256 + threadIdx.x;   // i = n*1024 + k
    int n = i >> 10, k = i & 1023;
    float x = W[i];
    __half hh = __float2half_rn(x);
    float r1 = x - __half2float(hh);
    __half hm = __float2half_rn(r1 * MSCALE);
    unsigned short hv[2];
    hv[0] = *reinterpret_cast<unsigned short*>(&hh);
    hv[1] = *reinterpret_cast<unsigned short*>(&hm);

    int kt = k >> 4, kl = k & 15;
    int lane = ((n & 7) << 2) | ((kl >> 1) & 3);
    int reg  = (kl >> 3) & 1;
    int nh   = n >> 5, ntp = (n >> 4) & 1;
    int w4   = ((n >> 3) & 1) * 2 + reg;
    #pragma unroll
    for (int s = 0; s < 2; ++s) {
        size_t off = ((((size_t)s * 64 + kt) * 2 + nh) * 2 + ntp) * 32 + lane;  // 16B units
        g_wp[off * 8 + w4 * 2 + (kl & 1)] = hv[s];
    }
}

extern __shared__ char dynsm[];

__global__ __launch_bounds__(NTHREADS, 2)
void gate_k(const float* __restrict__ X,
            float* __restrict__ outIdx, float* __restrict__ outW,
            float* __restrict__ outAux, int N) {
    const int tid  = threadIdx.x;
    const int lane = tid & 31;
    const int w    = tid >> 5;
    const int mt   = w >> 1;            // m-tile: 16 tokens (reader AND converter)
    const int nh   = w & 1;             // n-half: 32 experts (reader)
    const int ktc  = (w & 1) * 2;       // converter: this warp converts kt = ktc, ktc+1
    const unsigned sbu = smem_u32(dynsm);

    const float* Xblk = X + (size_t)blockIdx.x * BM * HDIM;
    // converter LDG base: row mt*16 + lane/4, col ktc*16 + (lane&3)*2
    const float* Xp = Xblk + (size_t)(mt * 16 + (lane >> 2)) * HDIM
                           + ktc * 16 + (lane & 3) * 2;

    auto loadB = [&](int c) {
        #pragma unroll
        for (int t = 0; t < 4; ++t) {
            int j = tid + t * 256;                  // 1024 16B units per stage
            int s = j >> 9, rem = j & 511;
            cp16(sbu + (c % 3) * B_TILE + (unsigned)j * 16,
                 (const char*)g_wp + (((size_t)s * 64 + c * 4) * 128 + rem) * 16);
        }
        cp_commit();
    };
    // LDG 8 float2 for chunk c (2 fragment blocks: kt = ktc, ktc+1)
    auto loadX = [&](int c, float2* xv) {
        const float* p = Xp + c * KC;
        #pragma unroll
        for (int i = 0; i < 2; ++i) {
            const float* b = p + i * 16;
            xv[i * 4 + 0] = *(const float2*)(b);                // (r,   k01)
            xv[i * 4 + 1] = *(const float2*)(b + 8 * HDIM);     // (r+8, k01)
            xv[i * 4 + 2] = *(const float2*)(b + 8);            // (r,   k89)
            xv[i * 4 + 3] = *(const float2*)(b + 8 * HDIM + 8); // (r+8, k89)
        }
    };
    auto convertX = [&](const float2* xv, uint32_t* fh, uint32_t* fm) {
        #pragma unroll
        for (int j = 0; j < 8; ++j) {
            float2 v = xv[j];
            __half2 h2 = __floats2half2_rn(v.x, v.y);
            float r1x = (v.x - __low2float(h2))  * MSCALE;
            float r1y = (v.y - __high2float(h2)) * MSCALE;
            __half2 m2 = __floats2half2_rn(r1x, r1y);
            fh[j] = h2bits(h2);
            fm[j] = h2bits(m2);
        }
    };

    loadB(0);
    loadB(1);

    float2   xv[8];
    uint32_t fh[8], fm[8];
    loadX(0, xv);
    convertX(xv, fh, fm);

    float accH[4][4] = {}, accM[4][4] = {}, kS[4][4] = {};

    // converter STS offsets (2 blocks: (mt, ktc), (mt, ktc+1))
    const unsigned cvo = (unsigned)(((mt * 4 + ktc) * 32 + lane) * 16);
    // reader base: (mt, kt=0) fragment, kt advances by 512
    const unsigned rdo = (unsigned)((mt * 4 * 32 + lane) * 16);
    // reader B offset base for this warp's nh
    const unsigned bo  = (unsigned)(((nh * 2) * 32 + lane) * 16);

    for (int c = 0; c < NCHUNK; ++c) {
        cp_wait1();                       // own B(c) groups landed
        {   // STS A-frags(c): buf c&1 free (last read chunk c-2, done pre-barrier(c-1))
            unsigned af = sbu + AF_BASE + (c & 1) * AF_BUF;
            sts128(af + cvo,               fh);
            sts128(af + cvo + 512,         fh + 4);
            sts128(af + 8192 + cvo,        fm);
            sts128(af + 8192 + cvo + 512,  fm + 4);
        }
        __syncthreads();                  // B(c) + A-frags(c) visible; c-1 reads done
        if (c + 2 < NCHUNK) loadB(c + 2); else cp_commit();

        if (c + 1 < NCHUNK) loadX(c + 1, xv);

        const unsigned afr = sbu + AF_BASE + (c & 1) * AF_BUF + rdo;
        const unsigned bB  = sbu + (c % 3) * B_TILE + bo;
        #pragma unroll
        for (int kt = 0; kt < 4; ++kt) {
            uint32_t ah[4], am[4], bh0[4], bh1[4], bm0[4], bm1[4];
            lds128(ah, afr + kt * 512);
            lds128(am, afr + kt * 512 + 8192);
            lds128(bh0, bB + (unsigned)(kt * 2048));          // hi  split, ntp0
            lds128(bh1, bB + (unsigned)(kt * 2048 + 512));    // hi  split, ntp1
            lds128(bm0, bB + (unsigned)(8192 + kt * 2048));   // mid split, ntp0
            lds128(bm1, bB + (unsigned)(8192 + kt * 2048 + 512));
            // hh -> accH ; mh -> accM (same order as R15)
            mma16816(accH[0], ah, bh0);  mma16816(accH[1], ah, bh0 + 2);
            mma16816(accM[0], am, bh0);  mma16816(accM[1], am, bh0 + 2);
            mma16816(accH[2], ah, bh1);  mma16816(accH[3], ah, bh1 + 2);
            mma16816(accM[2], am, bh1);  mma16816(accM[3], am, bh1 + 2);
            // hm -> accM
            mma16816(accM[0], ah, bm0);  mma16816(accM[1], ah, bm0 + 2);
            mma16816(accM[2], ah, bm1);  mma16816(accM[3], ah, bm1 + 2);
        }

        if (c + 1 < NCHUNK) convertX(xv, fh, fm);   // off MMA critical path

        if (c & 1) {  // fold accH into master — proven schedule
            #pragma unroll
            for (int nt = 0; nt < 4; ++nt)
                #pragma unroll
                for (int q = 0; q < 4; ++q) { kS[nt][q] += accH[nt][q]; accH[nt][q] = 0.0f; }
        }
    }
    __syncthreads();   // all smem reads done -> overlay logits

    // ---- write logits [64][66]: logit = kS + accM * 2^-11 ----
    float* lg = (float*)dynsm;
    {
        int r0 = mt * 16 + (lane >> 2);
        int n0 = nh * 32 + (lane & 3) * 2;
        #pragma unroll
        for (int nt = 0; nt < 4; ++nt) {
            float f0 = fmaf(accM[nt][0], MSCALE_I, kS[nt][0]);
            float f1 = fmaf(accM[nt][1], MSCALE_I, kS[nt][1]);
            float f2 = fmaf(accM[nt][2], MSCALE_I, kS[nt][2]);
            float f3 = fmaf(accM[nt][3], MSCALE_I, kS[nt][3]);
            *(float2*)(lg + r0 * 66 + n0 + nt * 8)       = make_float2(f0, f1);
            *(float2*)(lg + (r0 + 8) * 66 + n0 + nt * 8) = make_float2(f2, f3);
        }
    }
    __syncthreads();

    // ---- softmax + top-8: warp w -> tokens [8w, 8w+8) (proven epilogue) ----
    float ls0 = 0.0f, ls1 = 0.0f;
    int   c0  = 0,    c1  = 0;
    for (int t = w * 8; t < w * 8 + 8; ++t) {
        float l0 = lg[t * 66 + lane];
        float l1 = lg[t * 66 + 32 + lane];
        float m = fmaxf(l0, l1);
        #pragma unroll
        for (int off = 16; off; off >>= 1)
            m = fmaxf(m, __shfl_xor_sync(0xffffffffu, m, off));
        float s0 = expf(l0 - m), s1 = expf(l1 - m);
        float z = s0 + s1;
        #pragma unroll
        for (int off = 16; off; off >>= 1)
            z += __shfl_xor_sync(0xffffffffu, z, off);
        s0 /= z; s1 /= z;
        ls0 += s0; ls1 += s1;

        float r0 = s0, r1 = s1;
        float sumTop = 0.0f, myS = 0.0f;
        int myIdx = 0;
        #pragma unroll
        for (int r = 0; r < KTOP; ++r) {
            float v; int id;
            if (r0 >= r1) { v = r0; id = lane; }       // tie -> lower index
            else          { v = r1; id = lane + 32; }
            #pragma unroll
            for (int off = 16; off; off >>= 1) {
                float v2 = __shfl_xor_sync(0xffffffffu, v, off);
                int   i2 = __shfl_xor_sync(0xffffffffu, id, off);
                if (v2 > v || (v2 == v && i2 < id)) { v = v2; id = i2; }
            }
            sumTop += v;
            if (lane == r) { myS = v; myIdx = id; }
            if (id == lane)           { r0 = -1.0f; c0++; }
            else if (id == lane + 32) { r1 = -1.0f; c1++; }
        }
        if (lane < KTOP) {
            size_t gt = (size_t)(blockIdx.x * BM + t) * KTOP + lane;
            outIdx[gt] = (float)myIdx;
            outW[gt]   = myS / (sumTop + 1e-20f);
        }
    }

    // ---- CTA reduction + 64 global atomics ----
    float* redS = (float*)dynsm + 4224;          // beyond lg (64*66)
    float* redC = redS + 512;
    redS[w * 64 + lane]      = ls0;
    redS[w * 64 + lane + 32] = ls1;
    redC[w * 64 + lane]      = (float)c0;
    redC[w * 64 + lane + 32] = (float)c1;
    __syncthreads();
    if (tid < NEXP) {
        float es = 0.0f, ec = 0.0f;
        #pragma unroll
        for (int ww = 0; ww < 8; ++ww) {
            es += redS[ww * 64 + tid];
            ec += redC[ww * 64 + tid];
        }
        atomicAdd(&g_esum[tid], es);
        if (ec != 0.0f) atomicAdd(&g_ecnt[tid], (int)ec);
    }

    // ---- last-CTA aux finalize ----
    __shared__ unsigned s_isLast;
    __threadfence();
    __syncthreads();
    if (tid == 0)
        s_isLast = (atomicAdd(&g_done, 1u) == gridDim.x - 1) ? 1u : 0u;
    __syncthreads();
    if (s_isLast && tid < 32) {
        float p = g_esum[tid] * (float)g_ecnt[tid]
                + g_esum[tid + 32] * (float)g_ecnt[tid + 32];
        g_esum[tid] = 0.0f;  g_esum[tid + 32] = 0.0f;
        g_ecnt[tid] = 0;     g_ecnt[tid + 32] = 0;
        #pragma unroll
        for (int off = 16; off; off >>= 1)
            p += __shfl_xor_sync(0xffffffffu, p, off);
        if (tid == 0) {
            g_done = 0;
            float denom = (float)N * (float)(N * KTOP);
            *outAux = 0.01f * 64.0f * p / denom;   // ALPHA * E * sum / (N * N*K)
        }
    }
}

extern "C" void kernel_launch(void* const* d_in, const int* in_sizes, int n_in,
                              void* d_out, int out_size) {
    const float* X = (const float*)d_in[0];   // [4,8192,1024] f32
    const float* W = (const float*)d_in[1];   // [64,1024] f32
    float* out = (float*)d_out;               // [idx N*8 | weight N*8 | aux 1]
    int N = in_sizes[0] / HDIM;               // 32768

    cudaFuncSetAttribute(gate_k, cudaFuncAttributeMaxDynamicSharedMemorySize, SMEM_TOTAL);
    wsplit_k<<<NEXP * HDIM / 256, 256>>>(W);
    gate_k<<<N / BM, NTHREADS, SMEM_TOTAL>>>(X, out, out + (size_t)N * KTOP,
                                             out + (size_t)2 * N * KTOP, N);
}

// round 17
// speedup vs baseline: 1.0308x; 1.0308x over previous
#include <cuda_runtime.h>
#include <cuda_fp16.h>
#include <cstdint>

#define HDIM 1024
#define NEXP 64
#define KTOP 8
#define BM   64
#define KC   64
#define NCHUNK 16
#define NTHREADS 256

#define XROW 288                         // X smem row stride bytes (72 floats)
#define X_TILE (64 * XROW)               // 18432 B
#define B_TILE 16384                     // 2 splits x 4 kt x 2 nh x 2 ntp x 32 x 16B
#define STG (X_TILE + B_TILE)            // 34816 B
#define SMEM_TOTAL (3 * STG)             // 104448 B/CTA -> 2 CTAs/SM

#define MSCALE   2048.0f                 // 2^11 pre-scale for mid splits
#define MSCALE_I 4.8828125e-4f           // 2^-11

__device__ unsigned short g_wp[2 * 64 * 2 * 2 * 32 * 8];  // W fp16 splits, frag-permuted
__device__ float    g_esum[NEXP];
__device__ int      g_ecnt[NEXP];
__device__ unsigned g_done = 0;

__device__ __forceinline__ unsigned smem_u32(const void* p) {
    return (unsigned)__cvta_generic_to_shared(p);
}
__device__ __forceinline__ void cp16(unsigned dst, const void* src) {
    asm volatile("cp.async.cg.shared.global [%0], [%1], 16;\n" :: "r"(dst), "l"(src));
}
__device__ __forceinline__ void cp_commit() { asm volatile("cp.async.commit_group;\n"); }
__device__ __forceinline__ void cp_wait1()  { asm volatile("cp.async.wait_group 1;\n" ::: "memory"); }

__device__ __forceinline__ void lds128(uint32_t* r, unsigned a) {
    asm volatile("ld.shared.v4.u32 {%0,%1,%2,%3}, [%4];"
                 : "=r"(r[0]), "=r"(r[1]), "=r"(r[2]), "=r"(r[3]) : "r"(a));
}
__device__ __forceinline__ float2 lds64f(unsigned a) {
    float2 v;
    asm volatile("ld.shared.v2.f32 {%0,%1}, [%2];" : "=f"(v.x), "=f"(v.y) : "r"(a));
    return v;
}
// D(16x8,f32) += A(16x16,f16 row) x B(16x8,f16 col)
__device__ __forceinline__ void mma16816(float* d, const uint32_t* a, const uint32_t* b) {
    asm volatile("mma.sync.aligned.m16n8k16.row.col.f32.f16.f16.f32 "
                 "{%0,%1,%2,%3}, {%4,%5,%6,%7}, {%8,%9}, {%0,%1,%2,%3};"
                 : "+f"(d[0]), "+f"(d[1]), "+f"(d[2]), "+f"(d[3])
                 : "r"(a[0]), "r"(a[1]), "r"(a[2]), "r"(a[3]), "r"(b[0]), "r"(b[1]));
}
__device__ __forceinline__ uint32_t h2bits(__half2 h) {
    return *reinterpret_cast<uint32_t*>(&h);
}

// Split W into fp16 hi + (mid * 2^11), stored in B-fragment-permuted layout.
__global__ void wsplit_k(const float* __restrict__ W) {
    int i = blockIdx.x * 256 + threadIdx.x;   // i = n*1024 + k
    int n = i >> 10, k = i & 1023;
    float x = W[i];
    __half hh = __float2half_rn(x);
    float r1 = x - __half2float(hh);
    __half hm = __float2half_rn(r1 * MSCALE);
    unsigned short hv[2];
    hv[0] = *reinterpret_cast<unsigned short*>(&hh);
    hv[1] = *reinterpret_cast<unsigned short*>(&hm);

    int kt = k >> 4, kl = k & 15;
    int lane = ((n & 7) << 2) | ((kl >> 1) & 3);
    int reg  = (kl >> 3) & 1;
    int nh   = n >> 5, ntp = (n >> 4) & 1;
    int w4   = ((n >> 3) & 1) * 2 + reg;
    #pragma unroll
    for (int s = 0; s < 2; ++s) {
        size_t off = ((((size_t)s * 64 + kt) * 2 + nh) * 2 + ntp) * 32 + lane;  // 16B units
        g_wp[off * 8 + w4 * 2 + (kl & 1)] = hv[s];
    }
}

extern __shared__ char dynsm[];

__global__ __launch_bounds__(NTHREADS, 2)
void gate_k(const float* __restrict__ X,
            float* __restrict__ outIdx, float* __restrict__ outW,
            float* __restrict__ outAux, int N) {
    const int tid  = threadIdx.x;
    const int lane = tid & 31;
    const int w    = tid >> 5;
    const int mt   = w >> 1;            // m-tile: 16 tokens
    const int nh   = w & 1;             // n-half: 32 experts
    const int wph  = w & 3;             // kt phase stagger (decorrelate SMSP warps)
    const unsigned sbu = smem_u32(dynsm);

    const float* Xblk = X + (size_t)blockIdx.x * BM * HDIM;

    // one commit group per chunk: X tile (1024 chunks) + B tile (1024 chunks)
    auto load_tile = [&](int c) {
        unsigned st = sbu + (c % 3) * STG;
        #pragma unroll
        for (int t = 0; t < 4; ++t) {
            int j = tid + t * 256;
            int xr = j >> 4, xc16 = j & 15;
            cp16(st + (unsigned)(xr * XROW + xc16 * 16),
                 Xblk + (size_t)xr * HDIM + c * KC + xc16 * 4);
            int s = j >> 9, rem = j & 511;
            cp16(st + (unsigned)(X_TILE + j * 16),
                 (const char*)g_wp + (((size_t)s * 64 + c * 4) * 128 + rem) * 16);
        }
        cp_commit();
    };

    load_tile(0);
    load_tile(1);

    float accH[4][4] = {}, accM[4][4] = {}, kS[4][4] = {};

    // per-lane X smem offset: row mt*16 + (lane>>2), float2 col (lane&3)
    const unsigned xoff = (unsigned)((mt * 16 + (lane >> 2)) * XROW + (lane & 3) * 8);

    for (int c = 0; c < NCHUNK; ++c) {
        // R12-proven race-safe protocol: own-wait -> barrier -> refill
        cp_wait1();
        __syncthreads();
        if (c + 2 < NCHUNK) load_tile(c + 2); else cp_commit();

        const unsigned st = sbu + (c % 3) * STG;
        const unsigned xb = st + xoff;
        const unsigned bB = st + X_TILE;

        // head: load + convert A fragment for first (staggered) kt
        uint32_t ah[4], am[4];
        {
            unsigned xk = xb + wph * 64;
            float2 v[4];
            v[0] = lds64f(xk);
            v[1] = lds64f(xk + 8 * XROW);
            v[2] = lds64f(xk + 32);
            v[3] = lds64f(xk + 8 * XROW + 32);
            #pragma unroll
            for (int f = 0; f < 4; ++f) {
                __half2 h2 = __floats2half2_rn(v[f].x, v[f].y);
                float r1x = (v[f].x - __low2float(h2))  * MSCALE;
                float r1y = (v[f].y - __high2float(h2)) * MSCALE;
                __half2 m2 = __floats2half2_rn(r1x, r1y);
                ah[f] = h2bits(h2);
                am[f] = h2bits(m2);
            }
        }

        #pragma unroll
        for (int kt0 = 0; kt0 < 4; ++kt0) {
            const int kt  = (kt0 + wph) & 3;
            const int ktn = (kt0 + 1 + wph) & 3;

            uint32_t bh0[4], bh1[4], bm0[4], bm1[4];
            lds128(bh0, bB + (unsigned)(((((0 * 4 + kt) * 2 + nh) * 2 + 0) * 32 + lane) * 16));
            lds128(bh1, bB + (unsigned)(((((0 * 4 + kt) * 2 + nh) * 2 + 1) * 32 + lane) * 16));
            lds128(bm0, bB + (unsigned)(((((1 * 4 + kt) * 2 + nh) * 2 + 0) * 32 + lane) * 16));
            lds128(bm1, bB + (unsigned)(((((1 * 4 + kt) * 2 + nh) * 2 + 1) * 32 + lane) * 16));

            // prefetch next kt's A floats (independent of the MMAs below)
            float2 vn[4];
            if (kt0 < 3) {
                unsigned xk = xb + ktn * 64;
                vn[0] = lds64f(xk);
                vn[1] = lds64f(xk + 8 * XROW);
                vn[2] = lds64f(xk + 32);
                vn[3] = lds64f(xk + 8 * XROW + 32);
            }

            // hh -> accH ; mh -> accM ; hm -> accM  (same pairing as R15)
            mma16816(accH[0], ah, bh0);  mma16816(accH[1], ah, bh0 + 2);
            mma16816(accM[0], am, bh0);  mma16816(accM[1], am, bh0 + 2);
            mma16816(accH[2], ah, bh1);  mma16816(accH[3], ah, bh1 + 2);
            mma16816(accM[2], am, bh1);  mma16816(accM[3], am, bh1 + 2);
            mma16816(accM[0], ah, bm0);  mma16816(accM[1], ah, bm0 + 2);
            mma16816(accM[2], ah, bm1);  mma16816(accM[3], ah, bm1 + 2);

            // convert next kt's A fragment (overlaps the MMA pipe)
            if (kt0 < 3) {
                #pragma unroll
                for (int f = 0; f < 4; ++f) {
                    __half2 h2 = __floats2half2_rn(vn[f].x, vn[f].y);
                    float r1x = (vn[f].x - __low2float(h2))  * MSCALE;
                    float r1y = (vn[f].y - __high2float(h2)) * MSCALE;
                    __half2 m2 = __floats2half2_rn(r1x, r1y);
                    ah[f] = h2bits(h2);
                    am[f] = h2bits(m2);
                }
            }
        }

        if (c & 1) {  // fold accH into master — proven schedule
            #pragma unroll
            for (int nt = 0; nt < 4; ++nt)
                #pragma unroll
                for (int q = 0; q < 4; ++q) { kS[nt][q] += accH[nt][q]; accH[nt][q] = 0.0f; }
        }
    }
    __syncthreads();   // all smem reads done -> overlay logits

    // ---- write logits [64][66]: logit = kS + accM * 2^-11 ----
    float* lg = (float*)dynsm;
    {
        int r0 = mt * 16 + (lane >> 2);
        int n0 = nh * 32 + (lane & 3) * 2;
        #pragma unroll
        for (int nt = 0; nt < 4; ++nt) {
            float f0 = fmaf(accM[nt][0], MSCALE_I, kS[nt][0]);
            float f1 = fmaf(accM[nt][1], MSCALE_I, kS[nt][1]);
            float f2 = fmaf(accM[nt][2], MSCALE_I, kS[nt][2]);
            float f3 = fmaf(accM[nt][3], MSCALE_I, kS[nt][3]);
            *(float2*)(lg + r0 * 66 + n0 + nt * 8)       = make_float2(f0, f1);
            *(float2*)(lg + (r0 + 8) * 66 + n0 + nt * 8) = make_float2(f2, f3);
        }
    }
    __syncthreads();

    // ---- softmax + top-8: warp w -> tokens [8w, 8w+8) (proven epilogue) ----
    float ls0 = 0.0f, ls1 = 0.0f;
    int   c0  = 0,    c1  = 0;
    for (int t = w * 8; t < w * 8 + 8; ++t) {
        float l0 = lg[t * 66 + lane];
        float l1 = lg[t * 66 + 32 + lane];
        float m = fmaxf(l0, l1);
        #pragma unroll
        for (int off = 16; off; off >>= 1)
            m = fmaxf(m, __shfl_xor_sync(0xffffffffu, m, off));
        float s0 = expf(l0 - m), s1 = expf(l1 - m);
        float z = s0 + s1;
        #pragma unroll
        for (int off = 16; off; off >>= 1)
            z += __shfl_xor_sync(0xffffffffu, z, off);
        s0 /= z; s1 /= z;
        ls0 += s0; ls1 += s1;

        float r0 = s0, r1 = s1;
        float sumTop = 0.0f, myS = 0.0f;
        int myIdx = 0;
        #pragma unroll
        for (int r = 0; r < KTOP; ++r) {
            float v; int id;
            if (r0 >= r1) { v = r0; id = lane; }       // tie -> lower index
            else          { v = r1; id = lane + 32; }
            #pragma unroll
            for (int off = 16; off; off >>= 1) {
                float v2 = __shfl_xor_sync(0xffffffffu, v, off);
                int   i2 = __shfl_xor_sync(0xffffffffu, id, off);
                if (v2 > v || (v2 == v && i2 < id)) { v = v2; id = i2; }
            }
            sumTop += v;
            if (lane == r) { myS = v; myIdx = id; }
            if (id == lane)           { r0 = -1.0f; c0++; }
            else if (id == lane + 32) { r1 = -1.0f; c1++; }
        }
        if (lane < KTOP) {
            size_t gt = (size_t)(blockIdx.x * BM + t) * KTOP + lane;
            outIdx[gt] = (float)myIdx;
            outW[gt]   = myS / (sumTop + 1e-20f);
        }
    }

    // ---- CTA reduction + 64 global atomics ----
    float* redS = (float*)dynsm + 4224;          // beyond lg (64*66)
    float* redC = redS + 512;
    redS[w * 64 + lane]      = ls0;
    redS[w * 64 + lane + 32] = ls1;
    redC[w * 64 + lane]      = (float)c0;
    redC[w * 64 + lane + 32] = (float)c1;
    __syncthreads();
    if (tid < NEXP) {
        float es = 0.0f, ec = 0.0f;
        #pragma unroll
        for (int ww = 0; ww < 8; ++ww) {
            es += redS[ww * 64 + tid];
            ec += redC[ww * 64 + tid];
        }
        atomicAdd(&g_esum[tid], es);
        if (ec != 0.0f) atomicAdd(&g_ecnt[tid], (int)ec);
    }

    // ---- last-CTA aux finalize ----
    __shared__ unsigned s_isLast;
    __threadfence();
    __syncthreads();
    if (tid == 0)
        s_isLast = (atomicAdd(&g_done, 1u) == gridDim.x - 1) ? 1u : 0u;
    __syncthreads();
    if (s_isLast && tid < 32) {
        float p = g_esum[tid] * (float)g_ecnt[tid]
                + g_esum[tid + 32] * (float)g_ecnt[tid + 32];
        g_esum[tid] = 0.0f;  g_esum[tid + 32] = 0.0f;
        g_ecnt[tid] = 0;     g_ecnt[tid + 32] = 0;
        #pragma unroll
        for (int off = 16; off; off >>= 1)
            p += __shfl_xor_sync(0xffffffffu, p, off);
        if (tid == 0) {
            g_done = 0;
            float denom = (float)N * (float)(N * KTOP);
            *outAux = 0.01f * 64.0f * p / denom;   // ALPHA * E * sum / (N * N*K)
        }
    }
}

extern "C" void kernel_launch(void* const* d_in, const int* in_sizes, int n_in,
                              void* d_out, int out_size) {
    const float* X = (const float*)d_in[0];   // [4,8192,1024] f32
    const float* W = (const float*)d_in[1];   // [64,1024] f32
    float* out = (float*)d_out;               // [idx N*8 | weight N*8 | aux 1]
    int N = in_sizes[0] / HDIM;               // 32768

    cudaFuncSetAttribute(gate_k, cudaFuncAttributeMaxDynamicSharedMemorySize, SMEM_TOTAL);
    wsplit_k<<<NEXP * HDIM / 256, 256>>>(W);
    gate_k<<<N / BM, NTHREADS, SMEM_TOTAL>>>(X, out, out + (size_t)N * KTOP,
                                             out + (size_t)2 * N * KTOP, N);
}